// round 3
// baseline (speedup 1.0000x reference)
#include <cuda_runtime.h>
#include <cuda_bf16.h>
#include <cstdint>

// ---------------------------------------------------------------------------
// GCN 2-layer + FC on a fixed graph.
//   hs = (x @ W) * dinv        (per node)
//   acc[c] = sum_{edges r->c} hs[r]            (vector atomics, L2 resident)
//   x_next = relu(dinv*(acc + hs) + b)         (self loop = +hs)
// edge_index is int32 (JAX default x64-disabled downgrades int64 -> int32).
// ---------------------------------------------------------------------------

#define NMAX 131072

__device__ float g_deg [NMAX];
__device__ float g_dinv[NMAX];
__device__ float g_hs1 [NMAX * 32];
__device__ float g_acc1[NMAX * 32];
__device__ float g_hs2 [NMAX * 16];
__device__ float g_acc2[NMAX * 16];

__device__ __forceinline__ void red_add_v4(float* addr, float4 v) {
    asm volatile("red.global.add.v4.f32 [%0], {%1,%2,%3,%4};"
                 :: "l"(addr), "f"(v.x), "f"(v.y), "f"(v.z), "f"(v.w)
                 : "memory");
}

// init: zero accumulators, deg = 1 (self loop)
__global__ void k_init(int n) {
    int idx = blockIdx.x * blockDim.x + threadIdx.x;
    float4 z = make_float4(0.f, 0.f, 0.f, 0.f);
    if (idx < n * 8) reinterpret_cast<float4*>(g_acc1)[idx] = z;
    if (idx < n * 4) reinterpret_cast<float4*>(g_acc2)[idx] = z;
    if (idx < n)     g_deg[idx] = 1.0f;
}

// degree accumulation over edge targets
__global__ void k_deg(const int* __restrict__ dst, int E) {
    int e = blockIdx.x * blockDim.x + threadIdx.x;
    if (e < E) atomicAdd(&g_deg[dst[e]], 1.0f);   // no return value -> RED
}

// layer-1 linear: hs1 = (x @ W1) * dinv ; also store dinv
__global__ void k_gemm1(const float* __restrict__ x, const float* __restrict__ W1, int n) {
    __shared__ float sW[512];                      // W1: [16][32]
    for (int i = threadIdx.x; i < 512; i += blockDim.x) sW[i] = W1[i];
    __syncthreads();
    int i = blockIdx.x * blockDim.x + threadIdx.x;
    if (i >= n) return;

    float dinv = rsqrtf(g_deg[i]);
    g_dinv[i] = dinv;

    float xv[16];
    const float4* xp = reinterpret_cast<const float4*>(x + (size_t)i * 16);
#pragma unroll
    for (int q = 0; q < 4; q++) {
        float4 t = xp[q];
        xv[4*q] = t.x; xv[4*q+1] = t.y; xv[4*q+2] = t.z; xv[4*q+3] = t.w;
    }

    float4* op = reinterpret_cast<float4*>(g_hs1 + (size_t)i * 32);
#pragma unroll
    for (int q = 0; q < 8; q++) {
        float h[4];
#pragma unroll
        for (int jj = 0; jj < 4; jj++) {
            int j = 4*q + jj;
            float s = 0.f;
#pragma unroll
            for (int k = 0; k < 16; k++) s = fmaf(xv[k], sW[k*32 + j], s);
            h[jj] = s * dinv;
        }
        op[q] = make_float4(h[0], h[1], h[2], h[3]);
    }
}

// scatter layer 1: 8 threads per edge, one float4 chunk each (32 feats)
__global__ void k_scatter1(const int* __restrict__ src,
                           const int* __restrict__ dst, int E) {
    int idx = blockIdx.x * blockDim.x + threadIdx.x;
    int e = idx >> 3, c = idx & 7;
    if (e >= E) return;
    int r = src[e];
    int t = dst[e];
    float4 v = *reinterpret_cast<const float4*>(g_hs1 + (size_t)r * 32 + c * 4);
    red_add_v4(g_acc1 + (size_t)t * 32 + c * 4, v);
}

// combine layer 1 + relu + layer-2 linear: hs2 = (relu(dinv*(acc1+hs1)+b1) @ W2) * dinv
__global__ void k_gemm2(const float* __restrict__ W2, const float* __restrict__ b1, int n) {
    __shared__ float sW[512];                      // W2: [32][16]
    __shared__ float sb[32];
    for (int i = threadIdx.x; i < 512; i += blockDim.x) sW[i] = W2[i];
    if (threadIdx.x < 32) sb[threadIdx.x] = b1[threadIdx.x];
    __syncthreads();
    int i = blockIdx.x * blockDim.x + threadIdx.x;
    if (i >= n) return;

    float dinv = g_dinv[i];
    float x2[32];
    const float4* ap = reinterpret_cast<const float4*>(g_acc1 + (size_t)i * 32);
    const float4* hp = reinterpret_cast<const float4*>(g_hs1 + (size_t)i * 32);
#pragma unroll
    for (int q = 0; q < 8; q++) {
        float4 a = ap[q], h = hp[q];
        x2[4*q  ] = fmaxf(fmaf(dinv, a.x + h.x, sb[4*q  ]), 0.f);
        x2[4*q+1] = fmaxf(fmaf(dinv, a.y + h.y, sb[4*q+1]), 0.f);
        x2[4*q+2] = fmaxf(fmaf(dinv, a.z + h.z, sb[4*q+2]), 0.f);
        x2[4*q+3] = fmaxf(fmaf(dinv, a.w + h.w, sb[4*q+3]), 0.f);
    }

    float4* op = reinterpret_cast<float4*>(g_hs2 + (size_t)i * 16);
#pragma unroll
    for (int q = 0; q < 4; q++) {
        float h[4];
#pragma unroll
        for (int jj = 0; jj < 4; jj++) {
            int j = 4*q + jj;
            float s = 0.f;
#pragma unroll
            for (int k = 0; k < 32; k++) s = fmaf(x2[k], sW[k*16 + j], s);
            h[jj] = s * dinv;
        }
        op[q] = make_float4(h[0], h[1], h[2], h[3]);
    }
}

// scatter layer 2: 4 threads per edge (16 feats)
__global__ void k_scatter2(const int* __restrict__ src,
                           const int* __restrict__ dst, int E) {
    int idx = blockIdx.x * blockDim.x + threadIdx.x;
    int e = idx >> 2, c = idx & 3;
    if (e >= E) return;
    int r = src[e];
    int t = dst[e];
    float4 v = *reinterpret_cast<const float4*>(g_hs2 + (size_t)r * 16 + c * 4);
    red_add_v4(g_acc2 + (size_t)t * 16 + c * 4, v);
}

// combine layer 2 + relu + FC head
__global__ void k_final(const float* __restrict__ b2, const float* __restrict__ fcW,
                        const float* __restrict__ fcb, float* __restrict__ out, int n) {
    __shared__ float sb[16];
    __shared__ float sw[16];
    if (threadIdx.x < 16) { sb[threadIdx.x] = b2[threadIdx.x]; sw[threadIdx.x] = fcW[threadIdx.x]; }
    __syncthreads();
    int i = blockIdx.x * blockDim.x + threadIdx.x;
    if (i >= n) return;

    float dinv = g_dinv[i];
    float s = fcb[0];
    const float4* ap = reinterpret_cast<const float4*>(g_acc2 + (size_t)i * 16);
    const float4* hp = reinterpret_cast<const float4*>(g_hs2 + (size_t)i * 16);
#pragma unroll
    for (int q = 0; q < 4; q++) {
        float4 a = ap[q], h = hp[q];
        float v0 = fmaxf(fmaf(dinv, a.x + h.x, sb[4*q  ]), 0.f);
        float v1 = fmaxf(fmaf(dinv, a.y + h.y, sb[4*q+1]), 0.f);
        float v2 = fmaxf(fmaf(dinv, a.z + h.z, sb[4*q+2]), 0.f);
        float v3 = fmaxf(fmaf(dinv, a.w + h.w, sb[4*q+3]), 0.f);
        s = fmaf(v0, sw[4*q], fmaf(v1, sw[4*q+1], fmaf(v2, sw[4*q+2], fmaf(v3, sw[4*q+3], s))));
    }
    out[i] = s;
}

extern "C" void kernel_launch(void* const* d_in, const int* in_sizes, int n_in,
                              void* d_out, int out_size) {
    const int*   ei  = (const int*)d_in[0];     // [2, E] int32 (JAX x64 disabled)
    const float* x   = (const float*)d_in[1];   // [N, 16]
    const float* W1  = (const float*)d_in[2];   // [16, 32]
    const float* b1  = (const float*)d_in[3];   // [32]
    const float* W2  = (const float*)d_in[4];   // [32, 16]
    const float* b2  = (const float*)d_in[5];   // [16]
    const float* fcW = (const float*)d_in[6];   // [16, 1]
    const float* fcb = (const float*)d_in[7];   // [1]
    float*       out = (float*)d_out;           // [N, 1]

    const int E = in_sizes[0] / 2;
    const int n = in_sizes[1] / 16;
    const int* src = ei;
    const int* dst = ei + E;

    const int T = 256;
    k_init    <<<(n * 8 + T - 1) / T, T>>>(n);
    k_deg     <<<(E + T - 1) / T, T>>>(dst, E);
    k_gemm1   <<<(n + T - 1) / T, T>>>(x, W1, n);
    k_scatter1<<<((long long)E * 8 + T - 1) / T, T>>>(src, dst, E);
    k_gemm2   <<<(n + T - 1) / T, T>>>(W2, b1, n);
    k_scatter2<<<((long long)E * 4 + T - 1) / T, T>>>(src, dst, E);
    k_final   <<<(n + T - 1) / T, T>>>(b2, fcW, fcb, out, n);
}

// round 4
// speedup vs baseline: 1.2671x; 1.2671x over previous
#include <cuda_runtime.h>
#include <cuda_bf16.h>
#include <cstdint>

// ---------------------------------------------------------------------------
// GCN 2-layer + FC, aggregation-first form:
//   layer1:  agg1[c] = xs[c] + sum_{r->c} xs[r],  xs = x * dinv       (16-wide)
//            x2 = relu((dinv*agg1) @ W1 + b1)
//   layer2:  hs2 = (x2 @ W2) * dinv,  agg2[c] = hs2[c] + sum hs2[r]   (16-wide)
//            out = relu(dinv*agg2 + b2) @ fcW + fcb
// Self-loops are folded into the accumulator initialization (acc = xs / hs2).
// edge_index is int32.
// ---------------------------------------------------------------------------

#define NMAX 131072

__device__ int   g_deg [NMAX];
__device__ float g_dinv[NMAX];
__device__ float g_xs  [NMAX * 16];   // layer-1 message source
__device__ float g_acc1[NMAX * 16];   // layer-1 accumulator (init = xs)
__device__ float g_hs2 [NMAX * 16];   // layer-2 message source
__device__ float g_acc2[NMAX * 16];   // layer-2 accumulator (init = hs2)

__device__ __forceinline__ void red_add_v4(float* addr, float4 v) {
    asm volatile("red.global.add.v4.f32 [%0], {%1,%2,%3,%4};"
                 :: "l"(addr), "f"(v.x), "f"(v.y), "f"(v.z), "f"(v.w)
                 : "memory");
}

__global__ void k_zero(int n) {
    int i = blockIdx.x * blockDim.x + threadIdx.x;
    if (i < n) g_deg[i] = 0;
}

__global__ void k_deg(const int* __restrict__ dst, int E) {
    int e = blockIdx.x * blockDim.x + threadIdx.x;
    if (e < E) atomicAdd(&g_deg[dst[e]], 1);      // no return -> RED
}

// per node: dinv, xs = x*dinv, acc1 = xs (self-loop)
__global__ void k_pre(const float* __restrict__ x, int n) {
    int i = blockIdx.x * blockDim.x + threadIdx.x;
    if (i >= n) return;
    float dinv = rsqrtf((float)(g_deg[i] + 1));
    g_dinv[i] = dinv;
    const float4* xp = reinterpret_cast<const float4*>(x + (size_t)i * 16);
    float4* xsp  = reinterpret_cast<float4*>(g_xs   + (size_t)i * 16);
    float4* accp = reinterpret_cast<float4*>(g_acc1 + (size_t)i * 16);
#pragma unroll
    for (int q = 0; q < 4; q++) {
        float4 t = xp[q];
        t.x *= dinv; t.y *= dinv; t.z *= dinv; t.w *= dinv;
        xsp[q]  = t;
        accp[q] = t;
    }
}

// scatter 16-wide: 4 threads per edge, one float4 chunk each
__global__ void k_scatter1(const int* __restrict__ src,
                           const int* __restrict__ dst, int E) {
    int idx = blockIdx.x * blockDim.x + threadIdx.x;
    int e = idx >> 2, c = idx & 3;
    if (e >= E) return;
    int r = src[e];
    int t = dst[e];
    float4 v = __ldg(reinterpret_cast<const float4*>(g_xs + (size_t)r * 16 + c * 4));
    red_add_v4(g_acc1 + (size_t)t * 16 + c * 4, v);
}

// combine layer 1 + both GEMMs + relu:
//   x2 = relu((dinv*agg1) @ W1 + b1);  hs2 = (x2 @ W2) * dinv;  acc2 = hs2
__global__ void k_l1(const float* __restrict__ W1, const float* __restrict__ b1,
                     const float* __restrict__ W2, int n) {
    __shared__ float sW1[512];   // [16][32]
    __shared__ float sW2[512];   // [32][16]
    __shared__ float sb1[32];
    for (int i = threadIdx.x; i < 512; i += blockDim.x) { sW1[i] = W1[i]; sW2[i] = W2[i]; }
    if (threadIdx.x < 32) sb1[threadIdx.x] = b1[threadIdx.x];
    __syncthreads();
    int i = blockIdx.x * blockDim.x + threadIdx.x;
    if (i >= n) return;

    float dinv = g_dinv[i];
    float t[16];
    const float4* ap = reinterpret_cast<const float4*>(g_acc1 + (size_t)i * 16);
#pragma unroll
    for (int q = 0; q < 4; q++) {
        float4 a = ap[q];
        t[4*q  ] = a.x * dinv;
        t[4*q+1] = a.y * dinv;
        t[4*q+2] = a.z * dinv;
        t[4*q+3] = a.w * dinv;
    }

    float x2[32];
#pragma unroll
    for (int j = 0; j < 32; j++) {
        float s = sb1[j];
#pragma unroll
        for (int k = 0; k < 16; k++) s = fmaf(t[k], sW1[k*32 + j], s);
        x2[j] = fmaxf(s, 0.f);
    }

    float4* hp = reinterpret_cast<float4*>(g_hs2  + (size_t)i * 16);
    float4* cp = reinterpret_cast<float4*>(g_acc2 + (size_t)i * 16);
#pragma unroll
    for (int q = 0; q < 4; q++) {
        float h[4];
#pragma unroll
        for (int jj = 0; jj < 4; jj++) {
            int j = 4*q + jj;
            float s = 0.f;
#pragma unroll
            for (int k = 0; k < 32; k++) s = fmaf(x2[k], sW2[k*16 + j], s);
            h[jj] = s * dinv;
        }
        float4 v = make_float4(h[0], h[1], h[2], h[3]);
        hp[q] = v;
        cp[q] = v;
    }
}

// scatter layer 2: same 16-wide shape
__global__ void k_scatter2(const int* __restrict__ src,
                           const int* __restrict__ dst, int E) {
    int idx = blockIdx.x * blockDim.x + threadIdx.x;
    int e = idx >> 2, c = idx & 3;
    if (e >= E) return;
    int r = src[e];
    int t = dst[e];
    float4 v = __ldg(reinterpret_cast<const float4*>(g_hs2 + (size_t)r * 16 + c * 4));
    red_add_v4(g_acc2 + (size_t)t * 16 + c * 4, v);
}

// combine layer 2 + relu + FC head
__global__ void k_final(const float* __restrict__ b2, const float* __restrict__ fcW,
                        const float* __restrict__ fcb, float* __restrict__ out, int n) {
    __shared__ float sb[16];
    __shared__ float sw[16];
    if (threadIdx.x < 16) { sb[threadIdx.x] = b2[threadIdx.x]; sw[threadIdx.x] = fcW[threadIdx.x]; }
    __syncthreads();
    int i = blockIdx.x * blockDim.x + threadIdx.x;
    if (i >= n) return;

    float dinv = g_dinv[i];
    float s = fcb[0];
    const float4* ap = reinterpret_cast<const float4*>(g_acc2 + (size_t)i * 16);
#pragma unroll
    for (int q = 0; q < 4; q++) {
        float4 a = ap[q];
        float v0 = fmaxf(fmaf(dinv, a.x, sb[4*q  ]), 0.f);
        float v1 = fmaxf(fmaf(dinv, a.y, sb[4*q+1]), 0.f);
        float v2 = fmaxf(fmaf(dinv, a.z, sb[4*q+2]), 0.f);
        float v3 = fmaxf(fmaf(dinv, a.w, sb[4*q+3]), 0.f);
        s = fmaf(v0, sw[4*q], fmaf(v1, sw[4*q+1], fmaf(v2, sw[4*q+2], fmaf(v3, sw[4*q+3], s))));
    }
    out[i] = s;
}

extern "C" void kernel_launch(void* const* d_in, const int* in_sizes, int n_in,
                              void* d_out, int out_size) {
    const int*   ei  = (const int*)d_in[0];     // [2, E] int32
    const float* x   = (const float*)d_in[1];   // [N, 16]
    const float* W1  = (const float*)d_in[2];   // [16, 32]
    const float* b1  = (const float*)d_in[3];   // [32]
    const float* W2  = (const float*)d_in[4];   // [32, 16]
    const float* b2  = (const float*)d_in[5];   // [16]
    const float* fcW = (const float*)d_in[6];   // [16, 1]
    const float* fcb = (const float*)d_in[7];   // [1]
    float*       out = (float*)d_out;           // [N, 1]

    const int E = in_sizes[0] / 2;
    const int n = in_sizes[1] / 16;
    const int* src = ei;
    const int* dst = ei + E;

    const int T = 256;
    k_zero    <<<(n + T - 1) / T, T>>>(n);
    k_deg     <<<(E + T - 1) / T, T>>>(dst, E);
    k_pre     <<<(n + T - 1) / T, T>>>(x, n);
    k_scatter1<<<((long long)E * 4 + T - 1) / T, T>>>(src, dst, E);
    k_l1      <<<(n + T - 1) / T, T>>>(W1, b1, W2, n);
    k_scatter2<<<((long long)E * 4 + T - 1) / T, T>>>(src, dst, E);
    k_final   <<<(n + T - 1) / T, T>>>(b2, fcW, fcb, out, n);
}

// round 5
// speedup vs baseline: 1.2951x; 1.0221x over previous
#include <cuda_runtime.h>
#include <cuda_bf16.h>
#include <cstdint>

// ---------------------------------------------------------------------------
// GCN 2-layer + FC, aggregation-first + CSR-gather form.
//   Build CSR by destination (deg -> exclusive scan -> fill) once per call.
//   layer1: agg1[i] = xs[i] + sum_{r in nbr(i)} xs[r],  xs = x*dinv   (16-wide)
//           x2 = relu((dinv*agg1) @ W1 + b1); hs2 = (x2 @ W2)*dinv
//   layer2: agg2[i] = hs2[i] + sum hs2[r]
//           out = relu(dinv*agg2 + b2) @ fcW + fcb
// Gather (no atomics on features) ~halves L2 traffic vs scatter+RED.
// edge_index is int32.
// ---------------------------------------------------------------------------

#define NMAX 131072
#define EMAX 2097152

__device__ int   g_deg [NMAX];
__device__ int   g_off [NMAX];
__device__ int   g_cur [NMAX];
__device__ int   g_bsum[512];
__device__ int   g_esrc[EMAX];
__device__ float g_dinv[NMAX];
__device__ float g_xs  [NMAX * 16];
__device__ float g_agg1[NMAX * 16];
__device__ float g_hs2 [NMAX * 16];
__device__ float g_agg2[NMAX * 16];

__global__ void k_zero(int n) {
    int i = blockIdx.x * blockDim.x + threadIdx.x;
    if (i < n) g_deg[i] = 0;
}

__global__ void k_deg(const int* __restrict__ dst, int E) {
    int e = blockIdx.x * blockDim.x + threadIdx.x;
    if (e < E) atomicAdd(&g_deg[dst[e]], 1);      // no return -> RED
}

// block-level exclusive scan of deg -> g_off (partial), block sums -> g_bsum
__global__ void k_scan1(int n) {
    __shared__ int sh[256];
    int t = threadIdx.x, i = blockIdx.x * 256 + t;
    int v = (i < n) ? g_deg[i] : 0;
    sh[t] = v; __syncthreads();
#pragma unroll
    for (int o = 1; o < 256; o <<= 1) {
        int x = (t >= o) ? sh[t - o] : 0;
        __syncthreads();
        sh[t] += x;
        __syncthreads();
    }
    if (i < n) g_off[i] = sh[t] - v;              // exclusive within block
    if (t == 255) g_bsum[blockIdx.x] = sh[255];   // inclusive block total
}

// scan the block sums (nb <= 512), single block
__global__ void k_scan2(int nb) {
    __shared__ int sh[512];
    int t = threadIdx.x;
    int v = (t < nb) ? g_bsum[t] : 0;
    sh[t] = v; __syncthreads();
#pragma unroll
    for (int o = 1; o < 512; o <<= 1) {
        int x = (t >= o) ? sh[t - o] : 0;
        __syncthreads();
        sh[t] += x;
        __syncthreads();
    }
    if (t < nb) g_bsum[t] = sh[t] - v;            // exclusive block offsets
}

// finalize offsets, init fill cursors
__global__ void k_scan3(int n) {
    int i = blockIdx.x * blockDim.x + threadIdx.x;
    if (i < n) {
        int o = g_off[i] + g_bsum[i >> 8];
        g_off[i] = o;
        g_cur[i] = o;
    }
}

// fill CSR adjacency: for each edge, append src to dst's list
__global__ void k_fill(const int* __restrict__ src, const int* __restrict__ dst, int E) {
    int e = blockIdx.x * blockDim.x + threadIdx.x;
    if (e >= E) return;
    int t = dst[e];
    int p = atomicAdd(&g_cur[t], 1);
    g_esrc[p] = src[e];
}

// per node: dinv, xs = x*dinv
__global__ void k_pre(const float* __restrict__ x, int n) {
    int i = blockIdx.x * blockDim.x + threadIdx.x;
    if (i >= n) return;
    float dinv = rsqrtf((float)(g_deg[i] + 1));
    g_dinv[i] = dinv;
    const float4* xp = reinterpret_cast<const float4*>(x + (size_t)i * 16);
    float4* xsp = reinterpret_cast<float4*>(g_xs + (size_t)i * 16);
#pragma unroll
    for (int q = 0; q < 4; q++) {
        float4 t = xp[q];
        t.x *= dinv; t.y *= dinv; t.z *= dinv; t.w *= dinv;
        xsp[q] = t;
    }
}

// gather: 4 threads per node, thread c accumulates float4 chunk c
__device__ __forceinline__ void gather_body(const float* __restrict__ msg,
                                            float* __restrict__ agg, int n) {
    int idx = blockIdx.x * blockDim.x + threadIdx.x;
    int i = idx >> 2, c = idx & 3;
    if (i >= n) return;
    const float4* m4 = reinterpret_cast<const float4*>(msg);
    float4 s = __ldg(m4 + (size_t)i * 4 + c);     // self loop
    int j = g_off[i];
    int end = j + g_deg[i];
    for (; j + 1 < end; j += 2) {                 // unroll x2 for MLP
        int r0 = g_esrc[j], r1 = g_esrc[j + 1];
        float4 a = __ldg(m4 + (size_t)r0 * 4 + c);
        float4 b = __ldg(m4 + (size_t)r1 * 4 + c);
        s.x += a.x + b.x; s.y += a.y + b.y; s.z += a.z + b.z; s.w += a.w + b.w;
    }
    if (j < end) {
        int r = g_esrc[j];
        float4 a = __ldg(m4 + (size_t)r * 4 + c);
        s.x += a.x; s.y += a.y; s.z += a.z; s.w += a.w;
    }
    reinterpret_cast<float4*>(agg)[(size_t)i * 4 + c] = s;
}

__global__ void k_gather1(int n) { gather_body(g_xs,  g_agg1, n); }
__global__ void k_gather2(int n) { gather_body(g_hs2, g_agg2, n); }

// combine layer 1 + both GEMMs + relu: x2 = relu((dinv*agg1)@W1+b1); hs2 = (x2@W2)*dinv
__global__ void k_l1(const float* __restrict__ W1, const float* __restrict__ b1,
                     const float* __restrict__ W2, int n) {
    __shared__ float sW1[512];   // [16][32]
    __shared__ float sW2[512];   // [32][16]
    __shared__ float sb1[32];
    for (int i = threadIdx.x; i < 512; i += blockDim.x) { sW1[i] = W1[i]; sW2[i] = W2[i]; }
    if (threadIdx.x < 32) sb1[threadIdx.x] = b1[threadIdx.x];
    __syncthreads();
    int i = blockIdx.x * blockDim.x + threadIdx.x;
    if (i >= n) return;

    float dinv = g_dinv[i];
    float t[16];
    const float4* ap = reinterpret_cast<const float4*>(g_agg1 + (size_t)i * 16);
#pragma unroll
    for (int q = 0; q < 4; q++) {
        float4 a = ap[q];
        t[4*q  ] = a.x * dinv;
        t[4*q+1] = a.y * dinv;
        t[4*q+2] = a.z * dinv;
        t[4*q+3] = a.w * dinv;
    }

    float x2[32];
#pragma unroll
    for (int j = 0; j < 32; j++) {
        float s = sb1[j];
#pragma unroll
        for (int k = 0; k < 16; k++) s = fmaf(t[k], sW1[k*32 + j], s);
        x2[j] = fmaxf(s, 0.f);
    }

    float4* hp = reinterpret_cast<float4*>(g_hs2 + (size_t)i * 16);
#pragma unroll
    for (int q = 0; q < 4; q++) {
        float h[4];
#pragma unroll
        for (int jj = 0; jj < 4; jj++) {
            int j = 4*q + jj;
            float s = 0.f;
#pragma unroll
            for (int k = 0; k < 32; k++) s = fmaf(x2[k], sW2[k*16 + j], s);
            h[jj] = s * dinv;
        }
        hp[q] = make_float4(h[0], h[1], h[2], h[3]);
    }
}

// combine layer 2 + relu + FC head
__global__ void k_final(const float* __restrict__ b2, const float* __restrict__ fcW,
                        const float* __restrict__ fcb, float* __restrict__ out, int n) {
    __shared__ float sb[16];
    __shared__ float sw[16];
    if (threadIdx.x < 16) { sb[threadIdx.x] = b2[threadIdx.x]; sw[threadIdx.x] = fcW[threadIdx.x]; }
    __syncthreads();
    int i = blockIdx.x * blockDim.x + threadIdx.x;
    if (i >= n) return;

    float dinv = g_dinv[i];
    float s = fcb[0];
    const float4* ap = reinterpret_cast<const float4*>(g_agg2 + (size_t)i * 16);
#pragma unroll
    for (int q = 0; q < 4; q++) {
        float4 a = ap[q];
        float v0 = fmaxf(fmaf(dinv, a.x, sb[4*q  ]), 0.f);
        float v1 = fmaxf(fmaf(dinv, a.y, sb[4*q+1]), 0.f);
        float v2 = fmaxf(fmaf(dinv, a.z, sb[4*q+2]), 0.f);
        float v3 = fmaxf(fmaf(dinv, a.w, sb[4*q+3]), 0.f);
        s = fmaf(v0, sw[4*q], fmaf(v1, sw[4*q+1], fmaf(v2, sw[4*q+2], fmaf(v3, sw[4*q+3], s))));
    }
    out[i] = s;
}

extern "C" void kernel_launch(void* const* d_in, const int* in_sizes, int n_in,
                              void* d_out, int out_size) {
    const int*   ei  = (const int*)d_in[0];     // [2, E] int32
    const float* x   = (const float*)d_in[1];   // [N, 16]
    const float* W1  = (const float*)d_in[2];   // [16, 32]
    const float* b1  = (const float*)d_in[3];   // [32]
    const float* W2  = (const float*)d_in[4];   // [32, 16]
    const float* b2  = (const float*)d_in[5];   // [16]
    const float* fcW = (const float*)d_in[6];   // [16, 1]
    const float* fcb = (const float*)d_in[7];   // [1]
    float*       out = (float*)d_out;           // [N, 1]

    const int E = in_sizes[0] / 2;
    const int n = in_sizes[1] / 16;
    const int* src = ei;
    const int* dst = ei + E;

    const int T  = 256;
    const int nb = (n + 255) / 256;             // <= 512 (n <= NMAX)

    k_zero   <<<(n + T - 1) / T, T>>>(n);
    k_deg    <<<(E + T - 1) / T, T>>>(dst, E);
    k_scan1  <<<nb, 256>>>(n);
    k_scan2  <<<1, 512>>>(nb);
    k_scan3  <<<(n + T - 1) / T, T>>>(n);
    k_fill   <<<(E + T - 1) / T, T>>>(src, dst, E);
    k_pre    <<<(n + T - 1) / T, T>>>(x, n);
    k_gather1<<<((long long)n * 4 + T - 1) / T, T>>>(n);
    k_l1     <<<(n + T - 1) / T, T>>>(W1, b1, W2, n);
    k_gather2<<<((long long)n * 4 + T - 1) / T, T>>>(n);
    k_final  <<<(n + T - 1) / T, T>>>(b2, fcW, fcb, out, n);
}